// round 1
// baseline (speedup 1.0000x reference)
#include <cuda_runtime.h>

#define T_TOKENS 2048
#define DMODEL   1024
#define DFF      4096
#define NEXP     8
#define MAXPER   2048   // worst case: every token routes to this expert

// ---- device scratch (static, no runtime allocation) ----
__device__ int   g_cnt[NEXP];
__device__ int   g_tok[NEXP * MAXPER];
__device__ float g_wt [NEXP * MAXPER];
__device__ float g_h  [(size_t)NEXP * MAXPER * DFF];   // 256 MB hidden activations

// ---------------------------------------------------------------------------
// init: zero output and per-expert counters
// ---------------------------------------------------------------------------
__global__ void init_kernel(float* __restrict__ out, int out_size) {
    int i = blockIdx.x * blockDim.x + threadIdx.x;
    if (blockIdx.x == 0 && threadIdx.x < NEXP) g_cnt[threadIdx.x] = 0;
    for (int j = i; j < out_size; j += gridDim.x * blockDim.x) out[j] = 0.0f;
}

// ---------------------------------------------------------------------------
// route: one block per token, one warp per expert for the gate dot product
// ---------------------------------------------------------------------------
__global__ void route_kernel(const float* __restrict__ x,
                             const float* __restrict__ wg,
                             const float* __restrict__ bg) {
    int t    = blockIdx.x;
    int warp = threadIdx.x >> 5;
    int lane = threadIdx.x & 31;
    __shared__ float logits[NEXP];

    const float* xr = x + (size_t)t * DMODEL;
    float s = 0.0f;
    #pragma unroll 8
    for (int d = lane; d < DMODEL; d += 32)
        s += xr[d] * __ldg(&wg[d * NEXP + warp]);
    #pragma unroll
    for (int o = 16; o; o >>= 1) s += __shfl_down_sync(0xffffffffu, s, o);
    if (lane == 0) logits[warp] = s + bg[warp];
    __syncthreads();

    if (threadIdx.x == 0) {
        int   i0 = 0; float v0 = logits[0];
        #pragma unroll
        for (int e = 1; e < NEXP; e++)
            if (logits[e] > v0) { v0 = logits[e]; i0 = e; }
        int   i1 = -1; float v1 = -3.0e38f;
        #pragma unroll
        for (int e = 0; e < NEXP; e++)
            if (e != i0 && logits[e] > v1) { v1 = logits[e]; i1 = e; }
        // softmax over the two selected logits (v0 >= v1)
        float e1 = __expf(v1 - v0);
        float inv = 1.0f / (1.0f + e1);
        float w0 = inv;
        float w1 = e1 * inv;

        int p0 = atomicAdd(&g_cnt[i0], 1);
        g_tok[i0 * MAXPER + p0] = t;
        g_wt [i0 * MAXPER + p0] = w0;
        int p1 = atomicAdd(&g_cnt[i1], 1);
        g_tok[i1 * MAXPER + p1] = t;
        g_wt [i1 * MAXPER + p1] = w1;
    }
}

// ---------------------------------------------------------------------------
// Grouped GEMM tiles: BM=BN=128, BK=8, 256 threads, 8x8 per-thread micro-tile
// ---------------------------------------------------------------------------
#define BM 128
#define BN 128
#define BK 8

// GEMM1: H[e] = relu( gather(x) @ w1[e] + b1[e] )   [n_e,1024]x[1024,4096]
__global__ __launch_bounds__(256, 2)
void gemm1_kernel(const float* __restrict__ x,
                  const float* __restrict__ w1,
                  const float* __restrict__ b1) {
    const int e = blockIdx.z;
    const int n = g_cnt[e];
    const int row0 = blockIdx.y * BM;
    if (row0 >= n) return;
    const int col0 = blockIdx.x * BN;

    const float* B = w1 + (size_t)e * DMODEL * DFF;
    float*       H = g_h + (size_t)e * MAXPER * DFF;

    __shared__ float As[BK][BM];
    __shared__ float Bs[BK][BN];

    const int tid   = threadIdx.x;
    const int row_a = tid >> 1;             // 128 rows, 2 threads each
    const int kq_a  = (tid & 1) * 4;        // k quarter
    const int grow  = row0 + row_a;
    const int tok   = g_tok[e * MAXPER + min(grow, n - 1)];
    const float* Arow = x + (size_t)tok * DMODEL + kq_a;

    const int kk_b   = tid >> 5;            // 8 k-rows
    const int colq_b = (tid & 31) * 4;      // 32 col-quads
    const float* Brow = B + (size_t)kk_b * DFF + col0 + colq_b;

    const int tx = tid & 15, ty = tid >> 4;

    float acc[8][8];
    #pragma unroll
    for (int i = 0; i < 8; i++)
        #pragma unroll
        for (int j = 0; j < 8; j++) acc[i][j] = 0.0f;

    float4 afrag = *(const float4*)(Arow);
    float4 bfrag = *(const float4*)(Brow);

    for (int k0 = 0; k0 < DMODEL; k0 += BK) {
        As[kq_a + 0][row_a] = afrag.x;
        As[kq_a + 1][row_a] = afrag.y;
        As[kq_a + 2][row_a] = afrag.z;
        As[kq_a + 3][row_a] = afrag.w;
        *(float4*)&Bs[kk_b][colq_b] = bfrag;
        __syncthreads();

        if (k0 + BK < DMODEL) {             // prefetch next tiles
            afrag = *(const float4*)(Arow + (k0 + BK));
            bfrag = *(const float4*)(Brow + (size_t)(k0 + BK) * DFF);
        }

        #pragma unroll
        for (int kk = 0; kk < BK; kk++) {
            float4 a0 = *(const float4*)&As[kk][ty * 8];
            float4 a1 = *(const float4*)&As[kk][ty * 8 + 4];
            float4 b0 = *(const float4*)&Bs[kk][tx * 8];
            float4 b1v= *(const float4*)&Bs[kk][tx * 8 + 4];
            float ra[8] = {a0.x,a0.y,a0.z,a0.w,a1.x,a1.y,a1.z,a1.w};
            float rb[8] = {b0.x,b0.y,b0.z,b0.w,b1v.x,b1v.y,b1v.z,b1v.w};
            #pragma unroll
            for (int i = 0; i < 8; i++)
                #pragma unroll
                for (int j = 0; j < 8; j++)
                    acc[i][j] += ra[i] * rb[j];
        }
        __syncthreads();
    }

    // epilogue: bias + relu, store H
    const float* b1p = b1 + (size_t)e * DFF + col0 + tx * 8;
    float bias[8];
    #pragma unroll
    for (int j = 0; j < 8; j++) bias[j] = b1p[j];

    #pragma unroll
    for (int i = 0; i < 8; i++) {
        int r = row0 + ty * 8 + i;
        if (r >= n) continue;
        float* Hp = H + (size_t)r * DFF + col0 + tx * 8;
        float v[8];
        #pragma unroll
        for (int j = 0; j < 8; j++) v[j] = fmaxf(acc[i][j] + bias[j], 0.0f);
        *(float4*)(Hp)     = make_float4(v[0], v[1], v[2], v[3]);
        *(float4*)(Hp + 4) = make_float4(v[4], v[5], v[6], v[7]);
    }
}

// GEMM2: out[tok] += w_slot * ( H[e] @ w2[e] + b2[e] )   [n_e,4096]x[4096,1024]
__global__ __launch_bounds__(256, 2)
void gemm2_kernel(const float* __restrict__ w2,
                  const float* __restrict__ b2,
                  float* __restrict__ out) {
    const int e = blockIdx.z;
    const int n = g_cnt[e];
    const int row0 = blockIdx.y * BM;
    if (row0 >= n) return;
    const int col0 = blockIdx.x * BN;

    const float* A = g_h + (size_t)e * MAXPER * DFF;
    const float* B = w2 + (size_t)e * DFF * DMODEL;

    __shared__ float As[BK][BM];
    __shared__ float Bs[BK][BN];

    const int tid   = threadIdx.x;
    const int row_a = tid >> 1;
    const int kq_a  = (tid & 1) * 4;
    const int grow  = min(row0 + row_a, n - 1);
    const float* Arow = A + (size_t)grow * DFF + kq_a;

    const int kk_b   = tid >> 5;
    const int colq_b = (tid & 31) * 4;
    const float* Brow = B + (size_t)kk_b * DMODEL + col0 + colq_b;

    const int tx = tid & 15, ty = tid >> 4;

    float acc[8][8];
    #pragma unroll
    for (int i = 0; i < 8; i++)
        #pragma unroll
        for (int j = 0; j < 8; j++) acc[i][j] = 0.0f;

    float4 afrag = *(const float4*)(Arow);
    float4 bfrag = *(const float4*)(Brow);

    for (int k0 = 0; k0 < DFF; k0 += BK) {
        As[kq_a + 0][row_a] = afrag.x;
        As[kq_a + 1][row_a] = afrag.y;
        As[kq_a + 2][row_a] = afrag.z;
        As[kq_a + 3][row_a] = afrag.w;
        *(float4*)&Bs[kk_b][colq_b] = bfrag;
        __syncthreads();

        if (k0 + BK < DFF) {
            afrag = *(const float4*)(Arow + (k0 + BK));
            bfrag = *(const float4*)(Brow + (size_t)(k0 + BK) * DMODEL);
        }

        #pragma unroll
        for (int kk = 0; kk < BK; kk++) {
            float4 a0 = *(const float4*)&As[kk][ty * 8];
            float4 a1 = *(const float4*)&As[kk][ty * 8 + 4];
            float4 b0 = *(const float4*)&Bs[kk][tx * 8];
            float4 b1v= *(const float4*)&Bs[kk][tx * 8 + 4];
            float ra[8] = {a0.x,a0.y,a0.z,a0.w,a1.x,a1.y,a1.z,a1.w};
            float rb[8] = {b0.x,b0.y,b0.z,b0.w,b1v.x,b1v.y,b1v.z,b1v.w};
            #pragma unroll
            for (int i = 0; i < 8; i++)
                #pragma unroll
                for (int j = 0; j < 8; j++)
                    acc[i][j] += ra[i] * rb[j];
        }
        __syncthreads();
    }

    const float* b2p = b2 + (size_t)e * DMODEL + col0 + tx * 8;
    float bias[8];
    #pragma unroll
    for (int j = 0; j < 8; j++) bias[j] = b2p[j];

    #pragma unroll
    for (int i = 0; i < 8; i++) {
        int r = row0 + ty * 8 + i;
        if (r >= n) continue;
        int   tok = g_tok[e * MAXPER + r];
        float wt  = g_wt [e * MAXPER + r];
        float* op = out + (size_t)tok * DMODEL + col0 + tx * 8;
        #pragma unroll
        for (int j = 0; j < 8; j++)
            atomicAdd(&op[j], wt * (acc[i][j] + bias[j]));
    }
}

// ---------------------------------------------------------------------------
extern "C" void kernel_launch(void* const* d_in, const int* in_sizes, int n_in,
                              void* d_out, int out_size) {
    const float* x  = (const float*)d_in[0];
    const float* wg = (const float*)d_in[1];
    const float* bg = (const float*)d_in[2];
    const float* w1 = (const float*)d_in[3];
    const float* b1 = (const float*)d_in[4];
    const float* w2 = (const float*)d_in[5];
    const float* b2 = (const float*)d_in[6];
    float* out = (float*)d_out;

    init_kernel<<<512, 256>>>(out, out_size);
    route_kernel<<<T_TOKENS, 256>>>(x, wg, bg);
    gemm1_kernel<<<dim3(DFF / BN,    MAXPER / BM, NEXP), 256>>>(x, w1, b1);
    gemm2_kernel<<<dim3(DMODEL / BN, MAXPER / BM, NEXP), 256>>>(w2, b2, out);
}

// round 3
// speedup vs baseline: 1.8780x; 1.8780x over previous
#include <cuda_runtime.h>
#include <cstdint>

#define T_TOKENS 2048
#define DMODEL   1024
#define DFF      4096
#define NEXP     8
#define MAXPER   2048

#define BM 128
#define BN 128
#define BK 32
#define AST 36    // A smem row stride (floats)
#define BST 136   // B smem row stride (floats)
#define SMEM_FLOATS (2 * BM * AST + 2 * BK * BST)
#define SMEM_BYTES  (SMEM_FLOATS * 4)

// ---- device scratch (static, no runtime allocation) ----
__device__ int   g_cnt[NEXP];
__device__ int   g_tok[NEXP * MAXPER];
__device__ float g_wt [NEXP * MAXPER];
__device__ float g_h  [(size_t)NEXP * MAXPER * DFF];   // hidden activations

// ---------------------------------------------------------------------------
__device__ __forceinline__ uint32_t smem_u32(const void* p) {
    uint32_t a;
    asm("{ .reg .u64 t; cvta.to.shared.u64 t, %1; cvt.u32.u64 %0, t; }"
        : "=r"(a) : "l"(p));
    return a;
}
__device__ __forceinline__ uint32_t f2tf32(float f) {   // round-to-nearest tf32
    uint32_t r;
    asm("cvt.rna.tf32.f32 %0, %1;" : "=r"(r) : "f"(f));
    return r;
}
#define CP_ASYNC16(dst, src) \
    asm volatile("cp.async.cg.shared.global [%0], [%1], 16;" \
                 :: "r"(dst), "l"(src))
#define CP_COMMIT()  asm volatile("cp.async.commit_group;")
#define CP_WAIT1()   asm volatile("cp.async.wait_group 1;")
#define CP_WAIT0()   asm volatile("cp.async.wait_group 0;")

// ---------------------------------------------------------------------------
__global__ void init_kernel(float* __restrict__ out, int out_size) {
    int i = blockIdx.x * blockDim.x + threadIdx.x;
    if (blockIdx.x == 0 && threadIdx.x < NEXP) g_cnt[threadIdx.x] = 0;
    for (int j = i; j < out_size; j += gridDim.x * blockDim.x) out[j] = 0.0f;
}

__global__ void route_kernel(const float* __restrict__ x,
                             const float* __restrict__ wg,
                             const float* __restrict__ bg) {
    int t = blockIdx.x, warp = threadIdx.x >> 5, lane = threadIdx.x & 31;
    __shared__ float logits[NEXP];
    const float* xr = x + (size_t)t * DMODEL;
    float s = 0.0f;
    #pragma unroll 8
    for (int d = lane; d < DMODEL; d += 32)
        s += xr[d] * __ldg(&wg[d * NEXP + warp]);
    #pragma unroll
    for (int o = 16; o; o >>= 1) s += __shfl_down_sync(0xffffffffu, s, o);
    if (lane == 0) logits[warp] = s + bg[warp];
    __syncthreads();
    if (threadIdx.x == 0) {
        int i0 = 0; float v0 = logits[0];
        #pragma unroll
        for (int e = 1; e < NEXP; e++)
            if (logits[e] > v0) { v0 = logits[e]; i0 = e; }
        int i1 = -1; float v1 = -3.0e38f;
        #pragma unroll
        for (int e = 0; e < NEXP; e++)
            if (e != i0 && logits[e] > v1) { v1 = logits[e]; i1 = e; }
        float e1 = __expf(v1 - v0);
        float inv = 1.0f / (1.0f + e1);
        int p0 = atomicAdd(&g_cnt[i0], 1);
        g_tok[i0 * MAXPER + p0] = t; g_wt[i0 * MAXPER + p0] = inv;
        int p1 = atomicAdd(&g_cnt[i1], 1);
        g_tok[i1 * MAXPER + p1] = t; g_wt[i1 * MAXPER + p1] = e1 * inv;
    }
}

// ===========================================================================
// Grouped GEMM on mma.sync m16n8k8 tf32.
// G1:  H = relu( gather(x) @ w1[e] + b1[e] )        A:[n,1024]  B:[1024,4096]
// G2:  out[tok] += wt * ( H @ w2[e] + b2[e] )       A:[n,4096]  B:[4096,1024]
// Tile 128x128x32, 256 thr, warps 2(M) x 4(N), 64x32 per warp, cp.async x2 buf
// ===========================================================================
template <bool G1>
__global__ __launch_bounds__(256, 1)
void moe_gemm(const float* __restrict__ x,
              const float* __restrict__ w,
              const float* __restrict__ bias,
              float* __restrict__ out) {
    constexpr int K  = G1 ? DMODEL : DFF;   // reduction dim
    constexpr int NG = G1 ? DFF : DMODEL;   // global ld of B
    constexpr int NC = K / BK;

    const int e = blockIdx.z;
    const int n = g_cnt[e];
    const int row0 = blockIdx.y * BM;
    if (row0 >= n) return;
    const int col0 = blockIdx.x * BN;

    extern __shared__ float sm[];
    float* As = sm;                    // [2][BM][AST]
    float* Bs = sm + 2 * BM * AST;     // [2][BK][BST]

    const int tid = threadIdx.x, lane = tid & 31, wid = tid >> 5;
    const int wm = (wid & 1) * 64, wn = (wid >> 1) * 32;

    // ---- gmem->smem load assignment (16 floats / thread / tile, 4x16B) ----
    const int ar = tid >> 1, ac = (tid & 1) * 16;          // A: 128 rows x 32
    const int rr = min(row0 + ar, n - 1);
    const float* Ag;
    if (G1) Ag = x + (size_t)g_tok[e * MAXPER + rr] * DMODEL + ac;
    else    Ag = g_h + ((size_t)e * MAXPER + rr) * DFF + ac;
    const uint32_t AsW = smem_u32(As) + (uint32_t)(ar * AST + ac) * 4;

    const int br = tid >> 3, bc = (tid & 7) * 16;          // B: 32 rows x 128
    const float* Bg = w + (size_t)e * DMODEL * DFF + (size_t)br * NG + col0 + bc;
    const uint32_t BsW = smem_u32(Bs) + (uint32_t)(br * BST + bc) * 4;

    float acc[4][4][4];
    #pragma unroll
    for (int a = 0; a < 4; a++)
        #pragma unroll
        for (int b = 0; b < 4; b++)
            #pragma unroll
            for (int c = 0; c < 4; c++) acc[a][b][c] = 0.0f;

    // prologue: chunk 0
    {
        const float* ag = Ag;
        const float* bg = Bg;
        #pragma unroll
        for (int i = 0; i < 4; i++) CP_ASYNC16(AsW + i * 16, ag + i * 4);
        #pragma unroll
        for (int i = 0; i < 4; i++) CP_ASYNC16(BsW + i * 16, bg + i * 4);
        CP_COMMIT();
    }

    for (int c = 0; c < NC; c++) {
        if (c + 1 < NC) {
            const int b = (c + 1) & 1, k0 = (c + 1) * BK;
            const float* ag = Ag + k0;
            const float* bg = Bg + (size_t)k0 * NG;
            const uint32_t aw = AsW + b * (BM * AST * 4);
            const uint32_t bw = BsW + b * (BK * BST * 4);
            #pragma unroll
            for (int i = 0; i < 4; i++) CP_ASYNC16(aw + i * 16, ag + i * 4);
            #pragma unroll
            for (int i = 0; i < 4; i++) CP_ASYNC16(bw + i * 16, bg + i * 4);
            CP_COMMIT();
            CP_WAIT1();
        } else {
            CP_WAIT0();
        }
        __syncthreads();

        const float* Ab = As + (c & 1) * BM * AST + wm * AST;
        const float* Bb = Bs + (c & 1) * BK * BST + wn;

        #pragma unroll
        for (int ks = 0; ks < 4; ks++) {
            const int kk = ks * 8;
            uint32_t af[4][4];
            #pragma unroll
            for (int mt = 0; mt < 4; mt++) {
                const float* p = Ab + (mt * 16 + (lane >> 2)) * AST + kk + (lane & 3);
                af[mt][0] = f2tf32(p[0]);
                af[mt][1] = f2tf32(p[8 * AST]);
                af[mt][2] = f2tf32(p[4]);
                af[mt][3] = f2tf32(p[8 * AST + 4]);
            }
            uint32_t bf[4][2];
            #pragma unroll
            for (int nt = 0; nt < 4; nt++) {
                const float* p = Bb + (kk + (lane & 3)) * BST + nt * 8 + (lane >> 2);
                bf[nt][0] = f2tf32(p[0]);
                bf[nt][1] = f2tf32(p[4 * BST]);
            }
            #pragma unroll
            for (int mt = 0; mt < 4; mt++)
                #pragma unroll
                for (int nt = 0; nt < 4; nt++)
                    asm volatile(
                        "mma.sync.aligned.m16n8k8.row.col.f32.tf32.tf32.f32 "
                        "{%0,%1,%2,%3},{%4,%5,%6,%7},{%8,%9},{%0,%1,%2,%3};"
                        : "+f"(acc[mt][nt][0]), "+f"(acc[mt][nt][1]),
                          "+f"(acc[mt][nt][2]), "+f"(acc[mt][nt][3])
                        : "r"(af[mt][0]), "r"(af[mt][1]),
                          "r"(af[mt][2]), "r"(af[mt][3]),
                          "r"(bf[nt][0]), "r"(bf[nt][1]));
        }
        __syncthreads();
    }

    // ---- epilogue ----
    #pragma unroll
    for (int mt = 0; mt < 4; mt++) {
        #pragma unroll
        for (int half = 0; half < 2; half++) {
            const int r = row0 + wm + mt * 16 + (lane >> 2) + half * 8;
            if (r >= n) continue;
            if (G1) {
                float* Hp = g_h + ((size_t)e * MAXPER + r) * DFF + col0 + wn;
                const float* bp = bias + (size_t)e * DFF + col0 + wn;
                #pragma unroll
                for (int nt = 0; nt < 4; nt++) {
                    const int cc = nt * 8 + 2 * (lane & 3);
                    float2 v;
                    v.x = fmaxf(acc[mt][nt][half * 2 + 0] + bp[cc], 0.0f);
                    v.y = fmaxf(acc[mt][nt][half * 2 + 1] + bp[cc + 1], 0.0f);
                    *(float2*)(Hp + cc) = v;
                }
            } else {
                const int   tok = g_tok[e * MAXPER + r];
                const float wt  = g_wt [e * MAXPER + r];
                float* op = out + (size_t)tok * DMODEL + col0 + wn;
                const float* bp = bias + (size_t)e * DMODEL + col0 + wn;
                #pragma unroll
                for (int nt = 0; nt < 4; nt++) {
                    const int cc = nt * 8 + 2 * (lane & 3);
                    atomicAdd(&op[cc],     wt * (acc[mt][nt][half * 2 + 0] + bp[cc]));
                    atomicAdd(&op[cc + 1], wt * (acc[mt][nt][half * 2 + 1] + bp[cc + 1]));
                }
            }
        }
    }
}

// ===========================================================================
extern "C" void kernel_launch(void* const* d_in, const int* in_sizes, int n_in,
                              void* d_out, int out_size) {
    const float* x  = (const float*)d_in[0];
    const float* wg = (const float*)d_in[1];
    const float* bg = (const float*)d_in[2];
    const float* w1 = (const float*)d_in[3];
    const float* b1 = (const float*)d_in[4];
    const float* w2 = (const float*)d_in[5];
    const float* b2 = (const float*)d_in[6];
    float* out = (float*)d_out;

    cudaFuncSetAttribute(moe_gemm<true>,  cudaFuncAttributeMaxDynamicSharedMemorySize, SMEM_BYTES);
    cudaFuncSetAttribute(moe_gemm<false>, cudaFuncAttributeMaxDynamicSharedMemorySize, SMEM_BYTES);

    init_kernel<<<512, 256>>>(out, out_size);
    route_kernel<<<T_TOKENS, 256>>>(x, wg, bg);
    moe_gemm<true ><<<dim3(DFF / BN,    MAXPER / BM, NEXP), 256, SMEM_BYTES>>>(x, w1, b1, nullptr);
    moe_gemm<false><<<dim3(DMODEL / BN, MAXPER / BM, NEXP), 256, SMEM_BYTES>>>(x, w2, b2, out);
}

// round 4
// speedup vs baseline: 1.9642x; 1.0459x over previous
#include <cuda_runtime.h>
#include <cstdint>

#define T_TOKENS 2048
#define DMODEL   1024
#define DFF      4096
#define NEXP     8
#define MAXPER   2048

#define BM 128
#define BN 128
#define BK 32
#define AST 36    // A smem row stride (floats)
#define BST 136   // B smem row stride (floats)
#define SMEM_FLOATS (2 * BM * AST + 2 * BK * BST)
#define SMEM_BYTES  (SMEM_FLOATS * 4)

// ---- device scratch (static, no runtime allocation) ----
__device__ int   g_cnt[NEXP];
__device__ int   g_tok[NEXP * MAXPER];
__device__ float g_wt [NEXP * MAXPER];
__device__ float g_h  [(size_t)NEXP * MAXPER * DFF];   // hidden activations

// ---------------------------------------------------------------------------
__device__ __forceinline__ uint32_t smem_u32(const void* p) {
    uint32_t a;
    asm("{ .reg .u64 t; cvta.to.shared.u64 t, %1; cvt.u32.u64 %0, t; }"
        : "=r"(a) : "l"(p));
    return a;
}
__device__ __forceinline__ uint32_t f2tf32(float f) {   // round-to-nearest tf32
    uint32_t r;
    asm("cvt.rna.tf32.f32 %0, %1;" : "=r"(r) : "f"(f));
    return r;
}
#define CP_ASYNC16(dst, src) \
    asm volatile("cp.async.cg.shared.global [%0], [%1], 16;" \
                 :: "r"(dst), "l"(src))
#define CP_COMMIT()  asm volatile("cp.async.commit_group;")
#define CP_WAIT1()   asm volatile("cp.async.wait_group 1;")
#define CP_WAIT0()   asm volatile("cp.async.wait_group 0;")

// ---------------------------------------------------------------------------
__global__ void init_kernel(float* __restrict__ out, int out_size) {
    int i = blockIdx.x * blockDim.x + threadIdx.x;
    if (blockIdx.x == 0 && threadIdx.x < NEXP) g_cnt[threadIdx.x] = 0;
    for (int j = i; j < out_size; j += gridDim.x * blockDim.x) out[j] = 0.0f;
}

__global__ void route_kernel(const float* __restrict__ x,
                             const float* __restrict__ wg,
                             const float* __restrict__ bg) {
    int t = blockIdx.x, warp = threadIdx.x >> 5, lane = threadIdx.x & 31;
    __shared__ float logits[NEXP];
    const float* xr = x + (size_t)t * DMODEL;
    float s = 0.0f;
    #pragma unroll 8
    for (int d = lane; d < DMODEL; d += 32)
        s += xr[d] * __ldg(&wg[d * NEXP + warp]);
    #pragma unroll
    for (int o = 16; o; o >>= 1) s += __shfl_down_sync(0xffffffffu, s, o);
    if (lane == 0) logits[warp] = s + bg[warp];
    __syncthreads();
    if (threadIdx.x == 0) {
        int i0 = 0; float v0 = logits[0];
        #pragma unroll
        for (int e = 1; e < NEXP; e++)
            if (logits[e] > v0) { v0 = logits[e]; i0 = e; }
        int i1 = -1; float v1 = -3.0e38f;
        #pragma unroll
        for (int e = 0; e < NEXP; e++)
            if (e != i0 && logits[e] > v1) { v1 = logits[e]; i1 = e; }
        float e1 = __expf(v1 - v0);
        float inv = 1.0f / (1.0f + e1);
        int p0 = atomicAdd(&g_cnt[i0], 1);
        g_tok[i0 * MAXPER + p0] = t; g_wt[i0 * MAXPER + p0] = inv;
        int p1 = atomicAdd(&g_cnt[i1], 1);
        g_tok[i1 * MAXPER + p1] = t; g_wt[i1 * MAXPER + p1] = e1 * inv;
    }
}

// ===========================================================================
// Grouped GEMM on mma.sync m16n8k8 tf32.
// G1:  H = relu( gather(x) @ w1[e] + b1[e] )        A:[n,1024]  B:[1024,4096]
// G2:  out[tok] += wt * ( H @ w2[e] + b2[e] )       A:[n,4096]  B:[4096,1024]
//      (split-K over SPLITK chunks; bias folded into split 0 only)
// Tile 128x128x32, 256 thr, warps 2(M) x 4(N), 64x32/warp, cp.async x2 buf
// ===========================================================================
template <bool G1, int SPLITK>
__global__ __launch_bounds__(256, 2)
void moe_gemm(const float* __restrict__ x,
              const float* __restrict__ w,
              const float* __restrict__ bias,
              float* __restrict__ out) {
    constexpr int K   = G1 ? DMODEL : DFF;      // full reduction dim
    constexpr int KSP = K / SPLITK;             // this CTA's K span
    constexpr int NG  = G1 ? DFF : DMODEL;      // global ld of B
    constexpr int NC  = KSP / BK;

    const int e   = blockIdx.z / SPLITK;
    const int ksp = blockIdx.z % SPLITK;
    const int n = g_cnt[e];
    const int row0 = blockIdx.y * BM;
    if (row0 >= n) return;
    const int col0 = blockIdx.x * BN;
    const int kbase = ksp * KSP;

    extern __shared__ float sm[];
    float* As = sm;                    // [2][BM][AST]
    float* Bs = sm + 2 * BM * AST;     // [2][BK][BST]

    const int tid = threadIdx.x, lane = tid & 31, wid = tid >> 5;
    const int wm = (wid & 1) * 64, wn = (wid >> 1) * 32;

    // ---- gmem->smem load assignment (16 floats / thread / tile, 4x16B) ----
    const int ar = tid >> 1, ac = (tid & 1) * 16;          // A: 128 rows x 32
    const int rr = min(row0 + ar, n - 1);
    const float* Ag;
    if (G1) Ag = x + (size_t)g_tok[e * MAXPER + rr] * DMODEL + kbase + ac;
    else    Ag = g_h + ((size_t)e * MAXPER + rr) * DFF + kbase + ac;
    const uint32_t AsW = smem_u32(As) + (uint32_t)(ar * AST + ac) * 4;

    const int br = tid >> 3, bc = (tid & 7) * 16;          // B: 32 rows x 128
    const float* Bg = w + (size_t)e * DMODEL * DFF
                        + (size_t)(kbase + br) * NG + col0 + bc;
    const uint32_t BsW = smem_u32(Bs) + (uint32_t)(br * BST + bc) * 4;

    float acc[4][4][4];
    #pragma unroll
    for (int a = 0; a < 4; a++)
        #pragma unroll
        for (int b = 0; b < 4; b++)
            #pragma unroll
            for (int c = 0; c < 4; c++) acc[a][b][c] = 0.0f;

    // prologue: chunk 0
    #pragma unroll
    for (int i = 0; i < 4; i++) CP_ASYNC16(AsW + i * 16, Ag + i * 4);
    #pragma unroll
    for (int i = 0; i < 4; i++) CP_ASYNC16(BsW + i * 16, Bg + i * 4);
    CP_COMMIT();

    for (int c = 0; c < NC; c++) {
        if (c + 1 < NC) {
            const int b = (c + 1) & 1, k0 = (c + 1) * BK;
            const float* ag = Ag + k0;
            const float* bg = Bg + (size_t)k0 * NG;
            const uint32_t aw = AsW + b * (BM * AST * 4);
            const uint32_t bw = BsW + b * (BK * BST * 4);
            #pragma unroll
            for (int i = 0; i < 4; i++) CP_ASYNC16(aw + i * 16, ag + i * 4);
            #pragma unroll
            for (int i = 0; i < 4; i++) CP_ASYNC16(bw + i * 16, bg + i * 4);
            CP_COMMIT();
            CP_WAIT1();
        } else {
            CP_WAIT0();
        }
        __syncthreads();

        const float* Ab = As + (c & 1) * BM * AST + wm * AST;
        const float* Bb = Bs + (c & 1) * BK * BST + wn;

        #pragma unroll
        for (int ks = 0; ks < 4; ks++) {
            const int kk = ks * 8;
            uint32_t af[4][4];
            #pragma unroll
            for (int mt = 0; mt < 4; mt++) {
                const float* p = Ab + (mt * 16 + (lane >> 2)) * AST + kk + (lane & 3);
                af[mt][0] = f2tf32(p[0]);
                af[mt][1] = f2tf32(p[8 * AST]);
                af[mt][2] = f2tf32(p[4]);
                af[mt][3] = f2tf32(p[8 * AST + 4]);
            }
            uint32_t bf[4][2];
            #pragma unroll
            for (int nt = 0; nt < 4; nt++) {
                const float* p = Bb + (kk + (lane & 3)) * BST + nt * 8 + (lane >> 2);
                bf[nt][0] = f2tf32(p[0]);
                bf[nt][1] = f2tf32(p[4 * BST]);
            }
            #pragma unroll
            for (int mt = 0; mt < 4; mt++)
                #pragma unroll
                for (int nt = 0; nt < 4; nt++)
                    asm volatile(
                        "mma.sync.aligned.m16n8k8.row.col.f32.tf32.tf32.f32 "
                        "{%0,%1,%2,%3},{%4,%5,%6,%7},{%8,%9},{%0,%1,%2,%3};"
                        : "+f"(acc[mt][nt][0]), "+f"(acc[mt][nt][1]),
                          "+f"(acc[mt][nt][2]), "+f"(acc[mt][nt][3])
                        : "r"(af[mt][0]), "r"(af[mt][1]),
                          "r"(af[mt][2]), "r"(af[mt][3]),
                          "r"(bf[nt][0]), "r"(bf[nt][1]));
        }
        __syncthreads();
    }

    // ---- epilogue ----
    const bool add_bias = (ksp == 0);
    #pragma unroll
    for (int mt = 0; mt < 4; mt++) {
        #pragma unroll
        for (int half = 0; half < 2; half++) {
            const int r = row0 + wm + mt * 16 + (lane >> 2) + half * 8;
            if (r >= n) continue;
            if (G1) {
                float* Hp = g_h + ((size_t)e * MAXPER + r) * DFF + col0 + wn;
                const float* bp = bias + (size_t)e * DFF + col0 + wn;
                #pragma unroll
                for (int nt = 0; nt < 4; nt++) {
                    const int cc = nt * 8 + 2 * (lane & 3);
                    float2 v;
                    v.x = fmaxf(acc[mt][nt][half * 2 + 0] + bp[cc], 0.0f);
                    v.y = fmaxf(acc[mt][nt][half * 2 + 1] + bp[cc + 1], 0.0f);
                    *(float2*)(Hp + cc) = v;
                }
            } else {
                const int   tok = g_tok[e * MAXPER + r];
                const float wt  = g_wt [e * MAXPER + r];
                float* op = out + (size_t)tok * DMODEL + col0 + wn;
                const float* bp = bias + (size_t)e * DMODEL + col0 + wn;
                #pragma unroll
                for (int nt = 0; nt < 4; nt++) {
                    const int cc = nt * 8 + 2 * (lane & 3);
                    float b0 = add_bias ? bp[cc]     : 0.0f;
                    float b1 = add_bias ? bp[cc + 1] : 0.0f;
                    atomicAdd(&op[cc],     wt * (acc[mt][nt][half * 2 + 0] + b0));
                    atomicAdd(&op[cc + 1], wt * (acc[mt][nt][half * 2 + 1] + b1));
                }
            }
        }
    }
}

// ===========================================================================
extern "C" void kernel_launch(void* const* d_in, const int* in_sizes, int n_in,
                              void* d_out, int out_size) {
    const float* x  = (const float*)d_in[0];
    const float* wg = (const float*)d_in[1];
    const float* bg = (const float*)d_in[2];
    const float* w1 = (const float*)d_in[3];
    const float* b1 = (const float*)d_in[4];
    const float* w2 = (const float*)d_in[5];
    const float* b2 = (const float*)d_in[6];
    float* out = (float*)d_out;

    cudaFuncSetAttribute(moe_gemm<true, 1>,
                         cudaFuncAttributeMaxDynamicSharedMemorySize, SMEM_BYTES);
    cudaFuncSetAttribute(moe_gemm<false, 4>,
                         cudaFuncAttributeMaxDynamicSharedMemorySize, SMEM_BYTES);

    init_kernel<<<512, 256>>>(out, out_size);
    route_kernel<<<T_TOKENS, 256>>>(x, wg, bg);
    moe_gemm<true, 1><<<dim3(DFF / BN, MAXPER / BM, NEXP), 256, SMEM_BYTES>>>
        (x, w1, b1, nullptr);
    moe_gemm<false, 4><<<dim3(DMODEL / BN, MAXPER / BM, NEXP * 4), 256, SMEM_BYTES>>>
        (x, w2, b2, out);
}

// round 5
// speedup vs baseline: 2.1793x; 1.1095x over previous
#include <cuda_runtime.h>
#include <cstdint>

#define T_TOKENS 2048
#define DMODEL   1024
#define DFF      4096
#define NEXP     8
#define MAXPER   2048

#define BM 128
#define BN 128
#define BK 32
#define AST 36    // A smem row stride (floats), rows = m
#define BST 36    // B smem row stride (floats), rows = n, cols = interleaved k
#define SMEM_FLOATS (2 * BM * AST + 2 * BN * BST)
#define SMEM_BYTES  (SMEM_FLOATS * 4)

// ---- device scratch (static, no runtime allocation) ----
__device__ int   g_cnt[NEXP];
__device__ int   g_tok[NEXP * MAXPER];
__device__ float g_wt [NEXP * MAXPER];
__device__ float g_xt [(size_t)T_TOKENS * DMODEL];     // x pre-rounded to tf32
__device__ float g_h  [(size_t)NEXP * MAXPER * DFF];   // hidden (tf32 bits)

// ---------------------------------------------------------------------------
__device__ __forceinline__ uint32_t smem_u32(const void* p) {
    uint32_t a;
    asm("{ .reg .u64 t; cvta.to.shared.u64 t, %1; cvt.u32.u64 %0, t; }"
        : "=r"(a) : "l"(p));
    return a;
}
__device__ __forceinline__ uint32_t f2tf32(float f) {   // round-to-nearest tf32
    uint32_t r;
    asm("cvt.rna.tf32.f32 %0, %1;" : "=r"(r) : "f"(f));
    return r;
}
#define CP_ASYNC16(dst, src) \
    asm volatile("cp.async.cg.shared.global [%0], [%1], 16;" \
                 :: "r"(dst), "l"(src))
#define CP_COMMIT()  asm volatile("cp.async.commit_group;")
#define CP_WAIT1()   asm volatile("cp.async.wait_group 1;")
#define CP_WAIT0()   asm volatile("cp.async.wait_group 0;")

// ---------------------------------------------------------------------------
__global__ void init_kernel(const float* __restrict__ x,
                            float* __restrict__ out, int out_size) {
    int i = blockIdx.x * blockDim.x + threadIdx.x;
    int stride = gridDim.x * blockDim.x;
    if (blockIdx.x == 0 && threadIdx.x < NEXP) g_cnt[threadIdx.x] = 0;
    for (int j = i; j < out_size; j += stride) out[j] = 0.0f;
    for (int j = i; j < T_TOKENS * DMODEL; j += stride)
        g_xt[j] = __uint_as_float(f2tf32(x[j]));
}

__global__ void route_kernel(const float* __restrict__ x,
                             const float* __restrict__ wg,
                             const float* __restrict__ bg) {
    int t = blockIdx.x, warp = threadIdx.x >> 5, lane = threadIdx.x & 31;
    __shared__ float logits[NEXP];
    const float* xr = x + (size_t)t * DMODEL;
    float s = 0.0f;
    #pragma unroll 8
    for (int d = lane; d < DMODEL; d += 32)
        s += xr[d] * __ldg(&wg[d * NEXP + warp]);
    #pragma unroll
    for (int o = 16; o; o >>= 1) s += __shfl_down_sync(0xffffffffu, s, o);
    if (lane == 0) logits[warp] = s + bg[warp];
    __syncthreads();
    if (threadIdx.x == 0) {
        int i0 = 0; float v0 = logits[0];
        #pragma unroll
        for (int e = 1; e < NEXP; e++)
            if (logits[e] > v0) { v0 = logits[e]; i0 = e; }
        int i1 = -1; float v1 = -3.0e38f;
        #pragma unroll
        for (int e = 0; e < NEXP; e++)
            if (e != i0 && logits[e] > v1) { v1 = logits[e]; i1 = e; }
        float e1 = __expf(v1 - v0);
        float inv = 1.0f / (1.0f + e1);
        int p0 = atomicAdd(&g_cnt[i0], 1);
        g_tok[i0 * MAXPER + p0] = t; g_wt[i0 * MAXPER + p0] = inv;
        int p1 = atomicAdd(&g_cnt[i1], 1);
        g_tok[i1 * MAXPER + p1] = t; g_wt[i1 * MAXPER + p1] = e1 * inv;
    }
}

// ===========================================================================
// Grouped GEMM, mma.sync m16n8k8 tf32.
//   A smem: [m=128][AST] row-major, filled by cp.async (pre-converted tf32).
//   B smem: [n=128][BST] col-major-by-n, k interleaved so that the fragment
//           pair (k, k+4) is adjacent -> one LDS.64 per (nt, ks). Filled by
//           coalesced LDG along n + f2tf32 + STS.128.
// ===========================================================================
template <bool G1, int SPLITK>
__global__ __launch_bounds__(256, 2)
void moe_gemm(const float* __restrict__ w,
              const float* __restrict__ bias,
              float* __restrict__ out) {
    constexpr int K   = G1 ? DMODEL : DFF;
    constexpr int KSP = K / SPLITK;
    constexpr int NG  = G1 ? DFF : DMODEL;     // B gmem row stride
    constexpr int NC  = KSP / BK;

    const int e   = blockIdx.z / SPLITK;
    const int ksp = blockIdx.z % SPLITK;
    const int n = g_cnt[e];
    const int row0 = blockIdx.y * BM;
    if (row0 >= n) return;
    const int col0 = blockIdx.x * BN;
    const int kbase = ksp * KSP;

    extern __shared__ float sm[];
    float* As = sm;                     // [2][BM][AST]
    float* Bs = sm + 2 * BM * AST;      // [2][BN][BST]

    const int tid = threadIdx.x, lane = tid & 31, wid = tid >> 5;
    const int wm = (wid & 1) * 64, wn = (wid >> 1) * 32;

    // ---- A fill: cp.async, 16 floats / thread ----
    const int ar = tid >> 1, ac = (tid & 1) * 16;
    const int rr = min(row0 + ar, n - 1);
    const float* Ag;
    if (G1) Ag = g_xt + (size_t)g_tok[e * MAXPER + rr] * DMODEL + kbase + ac;
    else    Ag = g_h + ((size_t)e * MAXPER + rr) * DFF + kbase + ac;
    const uint32_t AsW = smem_u32(As) + (uint32_t)(ar * AST + ac) * 4;

    // ---- B fill: one n-column, 16 k values / thread ----
    const int nb = tid & 127, kh = (tid >> 7) * 16;
    const float* Bg = w + (size_t)e * DMODEL * DFF
                        + (size_t)(kbase + kh) * NG + col0 + nb;
    float* BsT = Bs + nb * BST + kh;    // this thread's STS base (buffer 0)

    float bv[16];

    #define LDG_B(c)                                                         \
        do { _Pragma("unroll")                                              \
             for (int i = 0; i < 16; i++)                                   \
                 bv[i] = __ldg(Bg + (size_t)((c) * BK + i) * NG);           \
        } while (0)

    // interleave: col kh + 2*(k&3) + ((k>>2)&1) within each 8-group
    #define STS_B(buf)                                                      \
        do {                                                                 \
            uint32_t bu[16];                                                 \
            _Pragma("unroll")                                                \
            for (int i = 0; i < 16; i++) bu[i] = f2tf32(bv[i]);              \
            float* p = BsT + (buf) * (BN * BST);                             \
            *(uint4*)(p + 0)  = make_uint4(bu[0],  bu[4],  bu[1],  bu[5]);   \
            *(uint4*)(p + 4)  = make_uint4(bu[2],  bu[6],  bu[3],  bu[7]);   \
            *(uint4*)(p + 8)  = make_uint4(bu[8],  bu[12], bu[9],  bu[13]);  \
            *(uint4*)(p + 12) = make_uint4(bu[10], bu[14], bu[11], bu[15]);  \
        } while (0)

    #define CPA_A(c)                                                        \
        do {                                                                 \
            const float* ag = Ag + (c) * BK;                                 \
            const uint32_t aw = AsW + ((c) & 1) * (BM * AST * 4);            \
            _Pragma("unroll")                                                \
            for (int i = 0; i < 4; i++) CP_ASYNC16(aw + i * 16, ag + i * 4); \
            CP_COMMIT();                                                     \
        } while (0)

    float acc[4][4][4];
    #pragma unroll
    for (int a = 0; a < 4; a++)
        #pragma unroll
        for (int b = 0; b < 4; b++)
            #pragma unroll
            for (int c = 0; c < 4; c++) acc[a][b][c] = 0.0f;

    // ---- prologue ----
    LDG_B(0);
    STS_B(0);
    CPA_A(0);
    if (NC > 1) { CPA_A(1); LDG_B(1); CP_WAIT1(); }
    else        { CP_WAIT0(); }
    __syncthreads();

    // ---- main loop: 2 buffers, 2 syncs / chunk ----
    for (int c = 0; c < NC; c++) {
        const float* Ab = As + (c & 1) * (BM * AST) + wm * AST;
        const float* Bb = Bs + (c & 1) * (BN * BST) + wn * BST;

        #pragma unroll
        for (int ks = 0; ks < 4; ks++) {
            const int kk = ks * 8;
            uint32_t af[4][4];
            #pragma unroll
            for (int mt = 0; mt < 4; mt++) {
                const float* p = Ab + (mt * 16 + (lane >> 2)) * AST + kk + (lane & 3);
                af[mt][0] = __float_as_uint(p[0]);
                af[mt][1] = __float_as_uint(p[8 * AST]);
                af[mt][2] = __float_as_uint(p[4]);
                af[mt][3] = __float_as_uint(p[8 * AST + 4]);
            }
            uint32_t bf[4][2];
            #pragma unroll
            for (int nt = 0; nt < 4; nt++) {
                const float2 v = *(const float2*)
                    (Bb + (nt * 8 + (lane >> 2)) * BST + kk + (lane & 3) * 2);
                bf[nt][0] = __float_as_uint(v.x);
                bf[nt][1] = __float_as_uint(v.y);
            }
            #pragma unroll
            for (int mt = 0; mt < 4; mt++)
                #pragma unroll
                for (int nt = 0; nt < 4; nt++)
                    asm volatile(
                        "mma.sync.aligned.m16n8k8.row.col.f32.tf32.tf32.f32 "
                        "{%0,%1,%2,%3},{%4,%5,%6,%7},{%8,%9},{%0,%1,%2,%3};"
                        : "+f"(acc[mt][nt][0]), "+f"(acc[mt][nt][1]),
                          "+f"(acc[mt][nt][2]), "+f"(acc[mt][nt][3])
                        : "r"(af[mt][0]), "r"(af[mt][1]),
                          "r"(af[mt][2]), "r"(af[mt][3]),
                          "r"(bf[nt][0]), "r"(bf[nt][1]));
        }
        __syncthreads();                 // everyone done reading buf c&1

        if (c + 1 < NC) {
            STS_B((c + 1) & 1);          // bv holds chunk c+1
            if (c + 2 < NC) {
                CPA_A(c + 2);            // into buf c&1 (now free)
                LDG_B(c + 2);            // refill bv (held until next iter)
                CP_WAIT1();              // A(c+1) arrived
            } else {
                CP_WAIT0();
            }
            __syncthreads();             // B(c+1) visible
        }
    }

    // ---- epilogue ----
    const bool add_bias = (ksp == 0);
    #pragma unroll
    for (int mt = 0; mt < 4; mt++) {
        #pragma unroll
        for (int half = 0; half < 2; half++) {
            const int r = row0 + wm + mt * 16 + (lane >> 2) + half * 8;
            if (r >= n) continue;
            if (G1) {
                float* Hp = g_h + ((size_t)e * MAXPER + r) * DFF + col0 + wn;
                const float* bp = bias + (size_t)e * DFF + col0 + wn;
                #pragma unroll
                for (int nt = 0; nt < 4; nt++) {
                    const int cc = nt * 8 + 2 * (lane & 3);
                    float2 v;
                    v.x = __uint_as_float(f2tf32(
                        fmaxf(acc[mt][nt][half * 2 + 0] + bp[cc], 0.0f)));
                    v.y = __uint_as_float(f2tf32(
                        fmaxf(acc[mt][nt][half * 2 + 1] + bp[cc + 1], 0.0f)));
                    *(float2*)(Hp + cc) = v;
                }
            } else {
                const int   tok = g_tok[e * MAXPER + r];
                const float wt  = g_wt [e * MAXPER + r];
                float* op = out + (size_t)tok * DMODEL + col0 + wn;
                const float* bp = bias + (size_t)e * DMODEL + col0 + wn;
                #pragma unroll
                for (int nt = 0; nt < 4; nt++) {
                    const int cc = nt * 8 + 2 * (lane & 3);
                    float b0 = add_bias ? bp[cc]     : 0.0f;
                    float b1 = add_bias ? bp[cc + 1] : 0.0f;
                    atomicAdd(&op[cc],     wt * (acc[mt][nt][half * 2 + 0] + b0));
                    atomicAdd(&op[cc + 1], wt * (acc[mt][nt][half * 2 + 1] + b1));
                }
            }
        }
    }
    #undef LDG_B
    #undef STS_B
    #undef CPA_A
}

// ===========================================================================
extern "C" void kernel_launch(void* const* d_in, const int* in_sizes, int n_in,
                              void* d_out, int out_size) {
    const float* x  = (const float*)d_in[0];
    const float* wg = (const float*)d_in[1];
    const float* bg = (const float*)d_in[2];
    const float* w1 = (const float*)d_in[3];
    const float* b1 = (const float*)d_in[4];
    const float* w2 = (const float*)d_in[5];
    const float* b2 = (const float*)d_in[6];
    float* out = (float*)d_out;

    cudaFuncSetAttribute(moe_gemm<true, 1>,
                         cudaFuncAttributeMaxDynamicSharedMemorySize, SMEM_BYTES);
    cudaFuncSetAttribute(moe_gemm<false, 4>,
                         cudaFuncAttributeMaxDynamicSharedMemorySize, SMEM_BYTES);

    init_kernel<<<512, 256>>>(x, out, out_size);
    route_kernel<<<T_TOKENS, 256>>>(x, wg, bg);
    moe_gemm<true, 1><<<dim3(DFF / BN, MAXPER / BM, NEXP), 256, SMEM_BYTES>>>
        (w1, b1, nullptr);
    moe_gemm<false, 4><<<dim3(DMODEL / BN, MAXPER / BM, NEXP * 4), 256, SMEM_BYTES>>>
        (w2, b2, out);
}

// round 6
// speedup vs baseline: 3.9851x; 1.8286x over previous
#include <cuda_runtime.h>
#include <cuda_fp16.h>
#include <cstdint>

#define T_TOKENS 2048
#define DMODEL   1024
#define DFF      4096
#define NEXP     8
#define MAXPER   2048

#define BM 128
#define BN 128
#define BK 32
#define AKH 40                     // A smem row stride (halves)
#define BKH 40                     // B smem row stride (halves)
#define ABUF_H (BM * AKH)
#define BBUF_H (BN * BKH)
#define SMEM_BYTES ((2 * ABUF_H + 2 * BBUF_H) * 2)

// ---- device scratch (static, no runtime allocation) ----
__device__ int    g_cnt[NEXP];
__device__ int    g_tok[NEXP * MAXPER];
__device__ float  g_wt [NEXP * MAXPER];
__device__ __half g_xh [(size_t)T_TOKENS * DMODEL];      // x in fp16
__device__ __half g_h  [(size_t)NEXP * MAXPER * DFF];    // hidden in fp16

// ---------------------------------------------------------------------------
__device__ __forceinline__ uint32_t smem_u32(const void* p) {
    uint32_t a;
    asm("{ .reg .u64 t; cvta.to.shared.u64 t, %1; cvt.u32.u64 %0, t; }"
        : "=r"(a) : "l"(p));
    return a;
}
#define CP_ASYNC16(dst, src) \
    asm volatile("cp.async.cg.shared.global [%0], [%1], 16;" \
                 :: "r"(dst), "l"(src))
#define CP_COMMIT()  asm volatile("cp.async.commit_group;")
#define CP_WAIT1()   asm volatile("cp.async.wait_group 1;")
#define CP_WAIT0()   asm volatile("cp.async.wait_group 0;")

// ---------------------------------------------------------------------------
__global__ void init_kernel(const float* __restrict__ x,
                            float* __restrict__ out, int out_size) {
    int i = blockIdx.x * blockDim.x + threadIdx.x;
    int stride = gridDim.x * blockDim.x;
    if (blockIdx.x == 0 && threadIdx.x < NEXP) g_cnt[threadIdx.x] = 0;
    for (int j = i; j < out_size; j += stride) out[j] = 0.0f;
    for (int j = i; j < T_TOKENS * DMODEL; j += stride)
        g_xh[j] = __float2half_rn(x[j]);
}

__global__ void route_kernel(const float* __restrict__ x,
                             const float* __restrict__ wg,
                             const float* __restrict__ bg) {
    int t = blockIdx.x, warp = threadIdx.x >> 5, lane = threadIdx.x & 31;
    __shared__ float logits[NEXP];
    const float* xr = x + (size_t)t * DMODEL;
    float s = 0.0f;
    #pragma unroll 8
    for (int d = lane; d < DMODEL; d += 32)
        s += xr[d] * __ldg(&wg[d * NEXP + warp]);
    #pragma unroll
    for (int o = 16; o; o >>= 1) s += __shfl_down_sync(0xffffffffu, s, o);
    if (lane == 0) logits[warp] = s + bg[warp];
    __syncthreads();
    if (threadIdx.x == 0) {
        int i0 = 0; float v0 = logits[0];
        #pragma unroll
        for (int e = 1; e < NEXP; e++)
            if (logits[e] > v0) { v0 = logits[e]; i0 = e; }
        int i1 = -1; float v1 = -3.0e38f;
        #pragma unroll
        for (int e = 0; e < NEXP; e++)
            if (e != i0 && logits[e] > v1) { v1 = logits[e]; i1 = e; }
        float e1 = __expf(v1 - v0);
        float inv = 1.0f / (1.0f + e1);
        int p0 = atomicAdd(&g_cnt[i0], 1);
        g_tok[i0 * MAXPER + p0] = t; g_wt[i0 * MAXPER + p0] = inv;
        int p1 = atomicAdd(&g_cnt[i1], 1);
        g_tok[i1 * MAXPER + p1] = t; g_wt[i1 * MAXPER + p1] = e1 * inv;
    }
}

// ===========================================================================
// Grouped GEMM, mma.sync m16n8k16 fp16 (fp32 accum).
//   A smem: fp16 [m=128][AKH], filled by cp.async from fp16 gmem (g_xh / g_h).
//   B smem: fp16 [n=128][BKH], natural k order (fp16x2 pair = k,k+1),
//           filled by coalesced LDG f32 + cvt + STS.128.
// ===========================================================================
template <bool G1, int SPLITK>
__global__ __launch_bounds__(256, 2)
void moe_gemm(const float* __restrict__ w,
              const float* __restrict__ bias,
              float* __restrict__ out) {
    constexpr int K   = G1 ? DMODEL : DFF;
    constexpr int KSP = K / SPLITK;
    constexpr int NG  = G1 ? DFF : DMODEL;     // B gmem row stride
    constexpr int NC  = KSP / BK;

    const int e   = blockIdx.z / SPLITK;
    const int ksp = blockIdx.z % SPLITK;
    const int n = g_cnt[e];
    const int row0 = blockIdx.y * BM;
    if (row0 >= n) return;
    const int col0 = blockIdx.x * BN;
    const int kbase = ksp * KSP;

    extern __shared__ __half sm[];
    __half* As = sm;                    // [2][BM][AKH]
    __half* Bs = sm + 2 * ABUF_H;       // [2][BN][BKH]

    const int tid = threadIdx.x, lane = tid & 31, wid = tid >> 5;
    const int wm = (wid & 1) * 64, wn = (wid >> 1) * 32;

    // ---- A fill: cp.async, 16 halves (32B) per thread per chunk ----
    const int ar = tid >> 1, ac = (tid & 1) * 16;
    const int rr = min(row0 + ar, n - 1);
    const __half* Ag;
    if (G1) Ag = g_xh + (size_t)g_tok[e * MAXPER + rr] * DMODEL + kbase + ac;
    else    Ag = g_h + ((size_t)e * MAXPER + rr) * DFF + kbase + ac;
    const uint32_t AsW = smem_u32(As) + (uint32_t)(ar * AKH + ac) * 2;

    // ---- B fill: one n-column, 16 k values per thread per chunk ----
    const int nb = tid & 127, kh = (tid >> 7) * 16;
    const float* Bg = w + (size_t)e * DMODEL * DFF
                        + (size_t)(kbase + kh) * NG + col0 + nb;
    __half* BsT = Bs + nb * BKH + kh;

    float bv[16];

    #define LDG_B(c)                                                         \
        do { _Pragma("unroll")                                               \
             for (int i = 0; i < 16; i++)                                    \
                 bv[i] = __ldg(Bg + (size_t)((c) * BK + i) * NG);            \
        } while (0)

    #define STS_B(buf)                                                       \
        do {                                                                  \
            uint32_t bu[8];                                                   \
            _Pragma("unroll")                                                 \
            for (int i = 0; i < 8; i++) {                                     \
                __half2 h2 = __floats2half2_rn(bv[2 * i], bv[2 * i + 1]);     \
                bu[i] = *(uint32_t*)&h2;                                      \
            }                                                                 \
            __half* p = BsT + (buf) * BBUF_H;                                 \
            *(uint4*)(p)     = make_uint4(bu[0], bu[1], bu[2], bu[3]);        \
            *(uint4*)(p + 8) = make_uint4(bu[4], bu[5], bu[6], bu[7]);        \
        } while (0)

    #define CPA_A(c)                                                         \
        do {                                                                  \
            const __half* ag = Ag + (c) * BK;                                 \
            const uint32_t aw = AsW + ((c) & 1) * (ABUF_H * 2);               \
            CP_ASYNC16(aw, ag);                                               \
            CP_ASYNC16(aw + 16, ag + 8);                                      \
            CP_COMMIT();                                                      \
        } while (0)

    float acc[4][4][4];
    #pragma unroll
    for (int a = 0; a < 4; a++)
        #pragma unroll
        for (int b = 0; b < 4; b++)
            #pragma unroll
            for (int c = 0; c < 4; c++) acc[a][b][c] = 0.0f;

    // ---- prologue ----
    LDG_B(0);
    STS_B(0);
    CPA_A(0);
    if (NC > 1) { CPA_A(1); LDG_B(1); CP_WAIT1(); }
    else        { CP_WAIT0(); }
    __syncthreads();

    // ---- main loop ----
    for (int c = 0; c < NC; c++) {
        const __half* Ab = As + (c & 1) * ABUF_H + wm * AKH;
        const __half* Bb = Bs + (c & 1) * BBUF_H + wn * BKH;

        #pragma unroll
        for (int ks = 0; ks < 2; ks++) {        // two k16 steps per chunk
            const int kk = ks * 16;
            uint32_t af[4][4];
            #pragma unroll
            for (int mt = 0; mt < 4; mt++) {
                const __half* p = Ab + (mt * 16 + (lane >> 2)) * AKH
                                     + kk + (lane & 3) * 2;
                af[mt][0] = *(const uint32_t*)(p);
                af[mt][1] = *(const uint32_t*)(p + 8 * AKH);
                af[mt][2] = *(const uint32_t*)(p + 8);
                af[mt][3] = *(const uint32_t*)(p + 8 * AKH + 8);
            }
            uint32_t bf[4][2];
            #pragma unroll
            for (int nt = 0; nt < 4; nt++) {
                const __half* p = Bb + (nt * 8 + (lane >> 2)) * BKH
                                     + kk + (lane & 3) * 2;
                bf[nt][0] = *(const uint32_t*)(p);
                bf[nt][1] = *(const uint32_t*)(p + 8);
            }
            #pragma unroll
            for (int mt = 0; mt < 4; mt++)
                #pragma unroll
                for (int nt = 0; nt < 4; nt++)
                    asm volatile(
                        "mma.sync.aligned.m16n8k16.row.col.f32.f16.f16.f32 "
                        "{%0,%1,%2,%3},{%4,%5,%6,%7},{%8,%9},{%0,%1,%2,%3};"
                        : "+f"(acc[mt][nt][0]), "+f"(acc[mt][nt][1]),
                          "+f"(acc[mt][nt][2]), "+f"(acc[mt][nt][3])
                        : "r"(af[mt][0]), "r"(af[mt][1]),
                          "r"(af[mt][2]), "r"(af[mt][3]),
                          "r"(bf[nt][0]), "r"(bf[nt][1]));
        }
        __syncthreads();

        if (c + 1 < NC) {
            STS_B((c + 1) & 1);
            if (c + 2 < NC) {
                CPA_A(c + 2);
                LDG_B(c + 2);
                CP_WAIT1();
            } else {
                CP_WAIT0();
            }
            __syncthreads();
        }
    }

    // ---- epilogue ----
    const bool add_bias = (ksp == 0);
    #pragma unroll
    for (int mt = 0; mt < 4; mt++) {
        #pragma unroll
        for (int half = 0; half < 2; half++) {
            const int r = row0 + wm + mt * 16 + (lane >> 2) + half * 8;
            if (r >= n) continue;
            if (G1) {
                __half* Hp = g_h + ((size_t)e * MAXPER + r) * DFF + col0 + wn;
                const float* bp = bias + (size_t)e * DFF + col0 + wn;
                #pragma unroll
                for (int nt = 0; nt < 4; nt++) {
                    const int cc = nt * 8 + 2 * (lane & 3);
                    float vx = fmaxf(acc[mt][nt][half * 2 + 0] + bp[cc], 0.0f);
                    float vy = fmaxf(acc[mt][nt][half * 2 + 1] + bp[cc + 1], 0.0f);
                    *(__half2*)(Hp + cc) = __floats2half2_rn(vx, vy);
                }
            } else {
                const int   tok = g_tok[e * MAXPER + r];
                const float wt  = g_wt [e * MAXPER + r];
                float* op = out + (size_t)tok * DMODEL + col0 + wn;
                const float* bp = bias + (size_t)e * DMODEL + col0 + wn;
                #pragma unroll
                for (int nt = 0; nt < 4; nt++) {
                    const int cc = nt * 8 + 2 * (lane & 3);
                    float b0 = add_bias ? bp[cc]     : 0.0f;
                    float b1 = add_bias ? bp[cc + 1] : 0.0f;
                    atomicAdd(&op[cc],     wt * (acc[mt][nt][half * 2 + 0] + b0));
                    atomicAdd(&op[cc + 1], wt * (acc[mt][nt][half * 2 + 1] + b1));
                }
            }
        }
    }
    #undef LDG_B
    #undef STS_B
    #undef CPA_A
}

// ===========================================================================
extern "C" void kernel_launch(void* const* d_in, const int* in_sizes, int n_in,
                              void* d_out, int out_size) {
    const float* x  = (const float*)d_in[0];
    const float* wg = (const float*)d_in[1];
    const float* bg = (const float*)d_in[2];
    const float* w1 = (const float*)d_in[3];
    const float* b1 = (const float*)d_in[4];
    const float* w2 = (const float*)d_in[5];
    const float* b2 = (const float*)d_in[6];
    float* out = (float*)d_out;

    cudaFuncSetAttribute(moe_gemm<true, 1>,
                         cudaFuncAttributeMaxDynamicSharedMemorySize, SMEM_BYTES);
    cudaFuncSetAttribute(moe_gemm<false, 4>,
                         cudaFuncAttributeMaxDynamicSharedMemorySize, SMEM_BYTES);

    init_kernel<<<512, 256>>>(x, out, out_size);
    route_kernel<<<T_TOKENS, 256>>>(x, wg, bg);
    moe_gemm<true, 1><<<dim3(DFF / BN, MAXPER / BM, NEXP), 256, SMEM_BYTES>>>
        (w1, b1, nullptr);
    moe_gemm<false, 4><<<dim3(DMODEL / BN, MAXPER / BM, NEXP * 4), 256, SMEM_BYTES>>>
        (w2, b2, out);
}

// round 7
// speedup vs baseline: 4.3097x; 1.0815x over previous
#include <cuda_runtime.h>
#include <cuda_fp16.h>
#include <cstdint>

#define T_TOKENS 2048
#define DMODEL   1024
#define DFF      4096
#define NEXP     8
#define MAXPER   2048

#define BM 128
#define BN 128
#define BK 32
#define AKH 40                     // A smem row stride (halves) -> 80B, LDSM conflict-free
#define BKH 40
#define ABUF_H (BM * AKH)
#define BBUF_H (BN * BKH)
#define SMEM_BYTES ((2 * ABUF_H + 2 * BBUF_H) * 2)

// ---- device scratch (static, no runtime allocation) ----
__device__ int    g_cnt[NEXP];
__device__ int    g_tok[NEXP * MAXPER];
__device__ float  g_wt [NEXP * MAXPER];
__device__ __half g_xh [(size_t)T_TOKENS * DMODEL];      // x in fp16
__device__ __half g_h  [(size_t)NEXP * MAXPER * DFF];    // hidden in fp16

// ---------------------------------------------------------------------------
__device__ __forceinline__ uint32_t smem_u32(const void* p) {
    uint32_t a;
    asm("{ .reg .u64 t; cvta.to.shared.u64 t, %1; cvt.u32.u64 %0, t; }"
        : "=r"(a) : "l"(p));
    return a;
}
#define CP_ASYNC16(dst, src) \
    asm volatile("cp.async.cg.shared.global [%0], [%1], 16;" \
                 :: "r"(dst), "l"(src))
#define CP_COMMIT()  asm volatile("cp.async.commit_group;")
#define CP_WAIT1()   asm volatile("cp.async.wait_group 1;")
#define CP_WAIT0()   asm volatile("cp.async.wait_group 0;")
#define LDSM4(r0, r1, r2, r3, addr)                                          \
    asm volatile("ldmatrix.sync.aligned.m8n8.x4.shared.b16 "                 \
                 "{%0,%1,%2,%3}, [%4];"                                      \
                 : "=r"(r0), "=r"(r1), "=r"(r2), "=r"(r3) : "r"(addr))

// ---------------------------------------------------------------------------
__global__ void init_kernel(const float* __restrict__ x,
                            float* __restrict__ out, int out_size) {
    int i = blockIdx.x * blockDim.x + threadIdx.x;
    int stride = gridDim.x * blockDim.x;
    if (blockIdx.x == 0 && threadIdx.x < NEXP) g_cnt[threadIdx.x] = 0;
    for (int j = i; j < out_size; j += stride) out[j] = 0.0f;
    for (int j = i; j < T_TOKENS * DMODEL; j += stride)
        g_xh[j] = __float2half_rn(x[j]);
}

__global__ void route_kernel(const float* __restrict__ x,
                             const float* __restrict__ wg,
                             const float* __restrict__ bg) {
    int t = blockIdx.x, warp = threadIdx.x >> 5, lane = threadIdx.x & 31;
    __shared__ float logits[NEXP];
    const float* xr = x + (size_t)t * DMODEL;
    float s = 0.0f;
    #pragma unroll 8
    for (int d = lane; d < DMODEL; d += 32)
        s += xr[d] * __ldg(&wg[d * NEXP + warp]);
    #pragma unroll
    for (int o = 16; o; o >>= 1) s += __shfl_down_sync(0xffffffffu, s, o);
    if (lane == 0) logits[warp] = s + bg[warp];
    __syncthreads();
    if (threadIdx.x == 0) {
        int i0 = 0; float v0 = logits[0];
        #pragma unroll
        for (int e = 1; e < NEXP; e++)
            if (logits[e] > v0) { v0 = logits[e]; i0 = e; }
        int i1 = -1; float v1 = -3.0e38f;
        #pragma unroll
        for (int e = 0; e < NEXP; e++)
            if (e != i0 && logits[e] > v1) { v1 = logits[e]; i1 = e; }
        float e1 = __expf(v1 - v0);
        float inv = 1.0f / (1.0f + e1);
        int p0 = atomicAdd(&g_cnt[i0], 1);
        g_tok[i0 * MAXPER + p0] = t; g_wt[i0 * MAXPER + p0] = inv;
        int p1 = atomicAdd(&g_cnt[i1], 1);
        g_tok[i1 * MAXPER + p1] = t; g_wt[i1 * MAXPER + p1] = e1 * inv;
    }
}

// ===========================================================================
// Grouped GEMM, mma.sync m16n8k16 fp16, ldmatrix.x4 fragment loads.
// ===========================================================================
template <bool G1>
__global__ __launch_bounds__(256, 2)
void moe_gemm(const float* __restrict__ w,
              const float* __restrict__ bias,
              float* __restrict__ out) {
    constexpr int K  = G1 ? DMODEL : DFF;
    constexpr int NG = G1 ? DFF : DMODEL;      // B gmem row stride
    constexpr int NC = K / BK;

    const int e = blockIdx.z;
    const int n = g_cnt[e];
    const int row0 = blockIdx.y * BM;
    if (row0 >= n) return;
    const int col0 = blockIdx.x * BN;

    extern __shared__ __half sm[];
    __half* As = sm;                    // [2][BM][AKH]
    __half* Bs = sm + 2 * ABUF_H;       // [2][BN][BKH]

    const int tid = threadIdx.x, lane = tid & 31, wid = tid >> 5;
    const int wm = (wid & 1) * 64, wn = (wid >> 1) * 32;

    // ---- A fill: cp.async, 16 halves (32B) per thread per chunk ----
    const int ar = tid >> 1, ac = (tid & 1) * 16;
    const int rr = min(row0 + ar, n - 1);
    const __half* Ag;
    if (G1) Ag = g_xh + (size_t)g_tok[e * MAXPER + rr] * DMODEL + ac;
    else    Ag = g_h + ((size_t)e * MAXPER + rr) * DFF + ac;
    const uint32_t AsW = smem_u32(As) + (uint32_t)(ar * AKH + ac) * 2;

    // ---- B fill: one n-column, 16 k values per thread per chunk ----
    const int nb = tid & 127, kh = (tid >> 7) * 16;
    const float* Bg = w + (size_t)e * DMODEL * DFF + (size_t)kh * NG + col0 + nb;
    __half* BsT = Bs + nb * BKH + kh;

    // ---- ldmatrix lane addresses (bytes) ----
    // A x4 per mt: lanes 0-15 -> rows 0-15 at col 0; 16-31 -> rows 0-15 at col 8
    const uint32_t aFrag = smem_u32(As)
        + (uint32_t)(((wm + (lane & 15)) * AKH + (lane >> 4) * 8) * 2);
    // B x4 per pair p: matrices (nt=2p,k0) (2p,k8) (2p+1,k0) (2p+1,k8)
    const uint32_t bFrag0 = smem_u32(Bs)
        + (uint32_t)(((wn + ((lane >> 4) & 1) * 8 + (lane & 7)) * BKH
                      + ((lane >> 3) & 1) * 8) * 2);
    const uint32_t bFrag1 = bFrag0 + 16 * BKH * 2;

    float bv[16];

    #define LDG_B(c)                                                         \
        do { _Pragma("unroll")                                               \
             for (int i = 0; i < 16; i++)                                    \
                 bv[i] = __ldg(Bg + (size_t)((c) * BK + i) * NG);            \
        } while (0)

    #define STS_B(buf)                                                       \
        do {                                                                  \
            uint32_t bu[8];                                                   \
            _Pragma("unroll")                                                 \
            for (int i = 0; i < 8; i++) {                                     \
                __half2 h2 = __floats2half2_rn(bv[2 * i], bv[2 * i + 1]);     \
                bu[i] = *(uint32_t*)&h2;                                      \
            }                                                                 \
            __half* p = BsT + (buf) * BBUF_H;                                 \
            *(uint4*)(p)     = make_uint4(bu[0], bu[1], bu[2], bu[3]);        \
            *(uint4*)(p + 8) = make_uint4(bu[4], bu[5], bu[6], bu[7]);        \
        } while (0)

    #define CPA_A(c)                                                         \
        do {                                                                  \
            const __half* ag = Ag + (c) * BK;                                 \
            const uint32_t aw = AsW + ((c) & 1) * (ABUF_H * 2);               \
            CP_ASYNC16(aw, ag);                                               \
            CP_ASYNC16(aw + 16, ag + 8);                                      \
            CP_COMMIT();                                                      \
        } while (0)

    float acc[4][4][4];
    #pragma unroll
    for (int a = 0; a < 4; a++)
        #pragma unroll
        for (int b = 0; b < 4; b++)
            #pragma unroll
            for (int c = 0; c < 4; c++) acc[a][b][c] = 0.0f;

    // ---- prologue ----
    LDG_B(0);
    STS_B(0);
    CPA_A(0);
    if (NC > 1) { CPA_A(1); LDG_B(1); CP_WAIT1(); }
    else        { CP_WAIT0(); }
    __syncthreads();

    // ---- main loop ----
    for (int c = 0; c < NC; c++) {
        const uint32_t aB = aFrag  + (c & 1) * (ABUF_H * 2);
        const uint32_t bB0 = bFrag0 + (c & 1) * (BBUF_H * 2);
        const uint32_t bB1 = bFrag1 + (c & 1) * (BBUF_H * 2);

        #pragma unroll
        for (int ks = 0; ks < 2; ks++) {        // two k16 steps per chunk
            const uint32_t ko = ks * 32;        // 16 halves = 32 bytes
            uint32_t af[4][4];
            #pragma unroll
            for (int mt = 0; mt < 4; mt++)
                LDSM4(af[mt][0], af[mt][1], af[mt][2], af[mt][3],
                      aB + mt * (16 * AKH * 2) + ko);
            uint32_t bf[4][2];
            LDSM4(bf[0][0], bf[0][1], bf[1][0], bf[1][1], bB0 + ko);
            LDSM4(bf[2][0], bf[2][1], bf[3][0], bf[3][1], bB1 + ko);
            #pragma unroll
            for (int mt = 0; mt < 4; mt++)
                #pragma unroll
                for (int nt = 0; nt < 4; nt++)
                    asm volatile(
                        "mma.sync.aligned.m16n8k16.row.col.f32.f16.f16.f32 "
                        "{%0,%1,%2,%3},{%4,%5,%6,%7},{%8,%9},{%0,%1,%2,%3};"
                        : "+f"(acc[mt][nt][0]), "+f"(acc[mt][nt][1]),
                          "+f"(acc[mt][nt][2]), "+f"(acc[mt][nt][3])
                        : "r"(af[mt][0]), "r"(af[mt][1]),
                          "r"(af[mt][2]), "r"(af[mt][3]),
                          "r"(bf[nt][0]), "r"(bf[nt][1]));
        }
        __syncthreads();

        if (c + 1 < NC) {
            STS_B((c + 1) & 1);
            if (c + 2 < NC) {
                CPA_A(c + 2);
                LDG_B(c + 2);
                CP_WAIT1();
            } else {
                CP_WAIT0();
            }
            __syncthreads();
        }
    }

    // ---- epilogue ----
    #pragma unroll
    for (int mt = 0; mt < 4; mt++) {
        #pragma unroll
        for (int half = 0; half < 2; half++) {
            const int r = row0 + wm + mt * 16 + (lane >> 2) + half * 8;
            if (r >= n) continue;
            if (G1) {
                __half* Hp = g_h + ((size_t)e * MAXPER + r) * DFF + col0 + wn;
                const float* bp = bias + (size_t)e * DFF + col0 + wn;
                #pragma unroll
                for (int nt = 0; nt < 4; nt++) {
                    const int cc = nt * 8 + 2 * (lane & 3);
                    float vx = fmaxf(acc[mt][nt][half * 2 + 0] + bp[cc], 0.0f);
                    float vy = fmaxf(acc[mt][nt][half * 2 + 1] + bp[cc + 1], 0.0f);
                    *(__half2*)(Hp + cc) = __floats2half2_rn(vx, vy);
                }
            } else {
                const int   tok = g_tok[e * MAXPER + r];
                const float wt  = g_wt [e * MAXPER + r];
                float* op = out + (size_t)tok * DMODEL + col0 + wn;
                const float* bp = bias + (size_t)e * DMODEL + col0 + wn;
                #pragma unroll
                for (int nt = 0; nt < 4; nt++) {
                    const int cc = nt * 8 + 2 * (lane & 3);
                    atomicAdd(&op[cc],
                              wt * (acc[mt][nt][half * 2 + 0] + bp[cc]));
                    atomicAdd(&op[cc + 1],
                              wt * (acc[mt][nt][half * 2 + 1] + bp[cc + 1]));
                }
            }
        }
    }
    #undef LDG_B
    #undef STS_B
    #undef CPA_A
}

// ===========================================================================
extern "C" void kernel_launch(void* const* d_in, const int* in_sizes, int n_in,
                              void* d_out, int out_size) {
    const float* x  = (const float*)d_in[0];
    const float* wg = (const float*)d_in[1];
    const float* bg = (const float*)d_in[2];
    const float* w1 = (const float*)d_in[3];
    const float* b1 = (const float*)d_in[4];
    const float* w2 = (const float*)d_in[5];
    const float* b2 = (const float*)d_in[6];
    float* out = (float*)d_out;

    cudaFuncSetAttribute(moe_gemm<true>,
                         cudaFuncAttributeMaxDynamicSharedMemorySize, SMEM_BYTES);
    cudaFuncSetAttribute(moe_gemm<false>,
                         cudaFuncAttributeMaxDynamicSharedMemorySize, SMEM_BYTES);

    init_kernel<<<512, 256>>>(x, out, out_size);
    route_kernel<<<T_TOKENS, 256>>>(x, wg, bg);
    moe_gemm<true ><<<dim3(DFF / BN,    MAXPER / BM, NEXP), 256, SMEM_BYTES>>>
        (w1, b1, nullptr);
    moe_gemm<false><<<dim3(DMODEL / BN, MAXPER / BM, NEXP), 256, SMEM_BYTES>>>
        (w2, b2, out);
}

// round 8
// speedup vs baseline: 4.5915x; 1.0654x over previous
#include <cuda_runtime.h>
#include <cuda_fp16.h>
#include <cstdint>

#define T_TOKENS 2048
#define DMODEL   1024
#define DFF      4096
#define NEXP     8
#define MAXPER   2048

#define BM 128
#define BN 128
#define BK 32
#define AKH 40                       // A smem row stride (halves)
#define NST 136                      // B smem k-row stride (halves)
#define ABUF_H (BM * AKH)            // 5120 halves
#define BBUF_H (BK * NST)            // 4352 halves
#define SMEM_BYTES ((3 * ABUF_H + 2 * BBUF_H) * 2)

// ---- device scratch (static, no runtime allocation) ----
__device__ int    g_cnt[NEXP];
__device__ int    g_tok[NEXP * MAXPER];
__device__ float  g_wt [NEXP * MAXPER];
__device__ __half g_xh [(size_t)T_TOKENS * DMODEL];
__device__ __half g_h  [(size_t)NEXP * MAXPER * DFF];

// ---------------------------------------------------------------------------
__device__ __forceinline__ uint32_t smem_u32(const void* p) {
    uint32_t a;
    asm("{ .reg .u64 t; cvta.to.shared.u64 t, %1; cvt.u32.u64 %0, t; }"
        : "=r"(a) : "l"(p));
    return a;
}
#define CP_ASYNC16(dst, src) \
    asm volatile("cp.async.cg.shared.global [%0], [%1], 16;" \
                 :: "r"(dst), "l"(src))
#define CP_COMMIT()  asm volatile("cp.async.commit_group;")
#define CP_WAIT1()   asm volatile("cp.async.wait_group 1;")
#define CP_WAIT0()   asm volatile("cp.async.wait_group 0;")
#define LDSM4(r0, r1, r2, r3, addr)                                          \
    asm volatile("ldmatrix.sync.aligned.m8n8.x4.shared.b16 "                 \
                 "{%0,%1,%2,%3}, [%4];"                                      \
                 : "=r"(r0), "=r"(r1), "=r"(r2), "=r"(r3) : "r"(addr))
#define LDSM4T(r0, r1, r2, r3, addr)                                         \
    asm volatile("ldmatrix.sync.aligned.m8n8.x4.trans.shared.b16 "           \
                 "{%0,%1,%2,%3}, [%4];"                                      \
                 : "=r"(r0), "=r"(r1), "=r"(r2), "=r"(r3) : "r"(addr))

// ---------------------------------------------------------------------------
__global__ void init_kernel(const float* __restrict__ x,
                            float* __restrict__ out, int out_size) {
    int i = blockIdx.x * blockDim.x + threadIdx.x;
    int stride = gridDim.x * blockDim.x;
    if (blockIdx.x == 0 && threadIdx.x < NEXP) g_cnt[threadIdx.x] = 0;
    for (int j = i; j < out_size; j += stride) out[j] = 0.0f;
    for (int j = i; j < T_TOKENS * DMODEL; j += stride)
        g_xh[j] = __float2half_rn(x[j]);
}

__global__ void route_kernel(const float* __restrict__ x,
                             const float* __restrict__ wg,
                             const float* __restrict__ bg) {
    int t = blockIdx.x, warp = threadIdx.x >> 5, lane = threadIdx.x & 31;
    __shared__ float logits[NEXP];
    const float* xr = x + (size_t)t * DMODEL;
    float s = 0.0f;
    #pragma unroll 8
    for (int d = lane; d < DMODEL; d += 32)
        s += xr[d] * __ldg(&wg[d * NEXP + warp]);
    #pragma unroll
    for (int o = 16; o; o >>= 1) s += __shfl_down_sync(0xffffffffu, s, o);
    if (lane == 0) logits[warp] = s + bg[warp];
    __syncthreads();
    if (threadIdx.x == 0) {
        int i0 = 0; float v0 = logits[0];
        #pragma unroll
        for (int e = 1; e < NEXP; e++)
            if (logits[e] > v0) { v0 = logits[e]; i0 = e; }
        int i1 = -1; float v1 = -3.0e38f;
        #pragma unroll
        for (int e = 0; e < NEXP; e++)
            if (e != i0 && logits[e] > v1) { v1 = logits[e]; i1 = e; }
        float e1 = __expf(v1 - v0);
        float inv = 1.0f / (1.0f + e1);
        int p0 = atomicAdd(&g_cnt[i0], 1);
        g_tok[i0 * MAXPER + p0] = t; g_wt[i0 * MAXPER + p0] = inv;
        int p1 = atomicAdd(&g_cnt[i1], 1);
        g_tok[i1 * MAXPER + p1] = t; g_wt[i1 * MAXPER + p1] = e1 * inv;
    }
}

// ===========================================================================
// Grouped GEMM, mma.sync m16n8k16 fp16.
//   A smem [m][AKH], 3 buffers, cp.async fills, ldmatrix.x4 fragments.
//   B smem [k][NST] (k-major), 2 buffers, coalesced LDG.128 + STS.64 fills,
//   ldmatrix.x4.trans fragments. ONE __syncthreads per K-chunk.
// ===========================================================================
template <bool G1>
__global__ __launch_bounds__(256, 2)
void moe_gemm(const float* __restrict__ w,
              const float* __restrict__ bias,
              float* __restrict__ out) {
    constexpr int K  = G1 ? DMODEL : DFF;
    constexpr int NG = G1 ? DFF : DMODEL;
    constexpr int NC = K / BK;

    const int e = blockIdx.z;
    const int n = g_cnt[e];
    const int row0 = blockIdx.y * BM;
    if (row0 >= n) return;
    const int col0 = blockIdx.x * BN;

    extern __shared__ __half sm[];
    __half* As = sm;                    // [3][BM][AKH]
    __half* Bs = sm + 3 * ABUF_H;       // [2][BK][NST]

    const int tid = threadIdx.x, lane = tid & 31, wid = tid >> 5;
    const int wm = (wid & 1) * 64, wn = (wid >> 1) * 32;

    // ---- A fill: cp.async, 32B per thread per chunk ----
    const int ar = tid >> 1, ac = (tid & 1) * 16;
    const int rr = min(row0 + ar, n - 1);
    const __half* Ag;
    if (G1) Ag = g_xh + (size_t)g_tok[e * MAXPER + rr] * DMODEL + ac;
    else    Ag = g_h + ((size_t)e * MAXPER + rr) * DFF + ac;
    const uint32_t AsW = smem_u32(As) + (uint32_t)(ar * AKH + ac) * 2;

    // ---- B fill: thread -> 4 k-rows x 4 consecutive n (LDG.128) ----
    const int bq = (tid & 31) * 4;          // n offset
    const int bk4 = (tid >> 5) * 4;         // base k-row
    const float* Bg = w + (size_t)e * DMODEL * DFF
                        + (size_t)bk4 * NG + col0 + bq;
    const uint32_t BsW = smem_u32(Bs) + (uint32_t)(bk4 * NST + bq) * 2;

    // ---- ldmatrix lane addresses (bytes) ----
    const uint32_t aFrag = smem_u32(As)
        + (uint32_t)(((wm + (lane & 15)) * AKH + (lane >> 4) * 8) * 2);
    // B trans: lane -> k-row (lane&7) + 8*((lane>>3)&1), n = wn + 8*(lane>>4)
    const uint32_t bFrag = smem_u32(Bs)
        + (uint32_t)((((lane & 7) + ((lane >> 3) & 1) * 8) * NST
                      + wn + (lane >> 4) * 8) * 2);

    float4 bqv[4];

    #define LDG_B(c)                                                         \
        do { _Pragma("unroll")                                               \
             for (int i = 0; i < 4; i++)                                     \
                 bqv[i] = *(const float4*)(Bg + (size_t)((c) * BK + i) * NG);\
        } while (0)

    #define STS_B(buf)                                                       \
        do { _Pragma("unroll")                                               \
             for (int i = 0; i < 4; i++) {                                   \
                 __half2 lo = __floats2half2_rn(bqv[i].x, bqv[i].y);         \
                 __half2 hi = __floats2half2_rn(bqv[i].z, bqv[i].w);         \
                 uint2 v = make_uint2(*(uint32_t*)&lo, *(uint32_t*)&hi);     \
                 asm volatile("st.shared.v2.b32 [%0], {%1, %2};" ::          \
                     "r"(BsW + (buf) * (BBUF_H * 2) + i * (NST * 2)),        \
                     "r"(v.x), "r"(v.y));                                    \
             }                                                               \
        } while (0)

    #define CPA_A(c, slot)                                                   \
        do {                                                                  \
            const __half* ag = Ag + (c) * BK;                                 \
            const uint32_t aw = AsW + (slot) * (ABUF_H * 2);                  \
            CP_ASYNC16(aw, ag);                                               \
            CP_ASYNC16(aw + 16, ag + 8);                                      \
            CP_COMMIT();                                                      \
        } while (0)

    float acc[4][4][4];
    #pragma unroll
    for (int a = 0; a < 4; a++)
        #pragma unroll
        for (int b = 0; b < 4; b++)
            #pragma unroll
            for (int c = 0; c < 4; c++) acc[a][b][c] = 0.0f;

    // ---- prologue ----
    LDG_B(0);
    STS_B(0);
    CPA_A(0, 0);
    if (NC > 1) { CPA_A(1, 1); LDG_B(1); CP_WAIT1(); }
    else        { CP_WAIT0(); }
    __syncthreads();

    // ---- main loop: ONE sync per chunk, A rotates over 3 slots ----
    int cur = 0;                         // A slot of chunk c
    for (int c = 0; c < NC; c++) {
        const uint32_t aB = aFrag + cur * (ABUF_H * 2);
        const uint32_t bB = bFrag + (c & 1) * (BBUF_H * 2);

        #pragma unroll
        for (int ks = 0; ks < 2; ks++) {
            uint32_t af[4][4];
            #pragma unroll
            for (int mt = 0; mt < 4; mt++)
                LDSM4(af[mt][0], af[mt][1], af[mt][2], af[mt][3],
                      aB + mt * (16 * AKH * 2) + ks * 32);
            uint32_t bf[4][2];
            LDSM4T(bf[0][0], bf[0][1], bf[1][0], bf[1][1],
                   bB + ks * (16 * NST * 2));
            LDSM4T(bf[2][0], bf[2][1], bf[3][0], bf[3][1],
                   bB + ks * (16 * NST * 2) + 32);      // +16 n = 32 bytes
            #pragma unroll
            for (int mt = 0; mt < 4; mt++)
                #pragma unroll
                for (int nt = 0; nt < 4; nt++)
                    asm volatile(
                        "mma.sync.aligned.m16n8k16.row.col.f32.f16.f16.f32 "
                        "{%0,%1,%2,%3},{%4,%5,%6,%7},{%8,%9},{%0,%1,%2,%3};"
                        : "+f"(acc[mt][nt][0]), "+f"(acc[mt][nt][1]),
                          "+f"(acc[mt][nt][2]), "+f"(acc[mt][nt][3])
                        : "r"(af[mt][0]), "r"(af[mt][1]),
                          "r"(af[mt][2]), "r"(af[mt][3]),
                          "r"(bf[nt][0]), "r"(bf[nt][1]));
        }

        if (c + 1 < NC) {
            STS_B((c + 1) & 1);                   // bqv holds chunk c+1
            if (c + 2 < NC) {
                int slot2 = cur >= 1 ? cur - 1 : cur + 2;   // (c+2)%3
                CPA_A(c + 2, slot2);
                LDG_B(c + 2);
                CP_WAIT1();                       // A(c+1) arrived
            } else {
                CP_WAIT0();
            }
            __syncthreads();
        }
        cur = (cur < 2) ? cur + 1 : 0;
    }

    // ---- epilogue ----
    #pragma unroll
    for (int mt = 0; mt < 4; mt++) {
        #pragma unroll
        for (int half = 0; half < 2; half++) {
            const int r = row0 + wm + mt * 16 + (lane >> 2) + half * 8;
            if (r >= n) continue;
            if (G1) {
                __half* Hp = g_h + ((size_t)e * MAXPER + r) * DFF + col0 + wn;
                const float* bp = bias + (size_t)e * DFF + col0 + wn;
                #pragma unroll
                for (int nt = 0; nt < 4; nt++) {
                    const int cc = nt * 8 + 2 * (lane & 3);
                    float vx = fmaxf(acc[mt][nt][half * 2 + 0] + bp[cc], 0.0f);
                    float vy = fmaxf(acc[mt][nt][half * 2 + 1] + bp[cc + 1], 0.0f);
                    *(__half2*)(Hp + cc) = __floats2half2_rn(vx, vy);
                }
            } else {
                const int   tok = g_tok[e * MAXPER + r];
                const float wt  = g_wt [e * MAXPER + r];
                float* op = out + (size_t)tok * DMODEL + col0 + wn;
                const float* bp = bias + (size_t)e * DMODEL + col0 + wn;
                #pragma unroll
                for (int nt = 0; nt < 4; nt++) {
                    const int cc = nt * 8 + 2 * (lane & 3);
                    atomicAdd(&op[cc],
                              wt * (acc[mt][nt][half * 2 + 0] + bp[cc]));
                    atomicAdd(&op[cc + 1],
                              wt * (acc[mt][nt][half * 2 + 1] + bp[cc + 1]));
                }
            }
        }
    }
    #undef LDG_B
    #undef STS_B
    #undef CPA_A
}

// ===========================================================================
extern "C" void kernel_launch(void* const* d_in, const int* in_sizes, int n_in,
                              void* d_out, int out_size) {
    const float* x  = (const float*)d_in[0];
    const float* wg = (const float*)d_in[1];
    const float* bg = (const float*)d_in[2];
    const float* w1 = (const float*)d_in[3];
    const float* b1 = (const float*)d_in[4];
    const float* w2 = (const float*)d_in[5];
    const float* b2 = (const float*)d_in[6];
    float* out = (float*)d_out;

    cudaFuncSetAttribute(moe_gemm<true>,
                         cudaFuncAttributeMaxDynamicSharedMemorySize, SMEM_BYTES);
    cudaFuncSetAttribute(moe_gemm<false>,
                         cudaFuncAttributeMaxDynamicSharedMemorySize, SMEM_BYTES);

    init_kernel<<<512, 256>>>(x, out, out_size);
    route_kernel<<<T_TOKENS, 256>>>(x, wg, bg);
    moe_gemm<true ><<<dim3(DFF / BN,    MAXPER / BM, NEXP), 256, SMEM_BYTES>>>
        (w1, b1, nullptr);
    moe_gemm<false><<<dim3(DMODEL / BN, MAXPER / BM, NEXP), 256, SMEM_BYTES>>>
        (w2, b2, out);
}